// round 13
// baseline (speedup 1.0000x reference)
#include <cuda_runtime.h>

// Problem constants (B,T,C,H = 2,2048,1024,16)
#define BB 2
#define TT 2048
#define CC 1024
#define HH 16
#define DD 64
#define MM (BB*TT)   // 4096

typedef unsigned long long u64;

// ---------------------------------------------------------------------------
// Scratch (static device globals — no allocation APIs anywhere)
// ---------------------------------------------------------------------------
__device__ float g_q[BB*HH*TT*DD];   // [b,h,t,d]
__device__ float g_k[BB*HH*TT*DD];
__device__ float g_v[BB*HH*TT*DD];
__device__ float g_y[BB*TT*CC];      // attention output, [b,t,c]

// ---------------------------------------------------------------------------
// f32x2 packed-math helpers (FFMA2 — ptxas never auto-generates these)
// ---------------------------------------------------------------------------
__device__ __forceinline__ u64 pk2f(float lo, float hi) {
    u64 r;
    asm("mov.b64 %0, {%1, %2};" : "=l"(r)
        : "r"(__float_as_int(lo)), "r"(__float_as_int(hi)));
    return r;
}
__device__ __forceinline__ void fma2(u64& d, u64 a, u64 b) {
    asm("fma.rn.f32x2 %0, %1, %2, %0;" : "+l"(d) : "l"(a), "l"(b));
}
__device__ __forceinline__ void mul2(u64& d, u64 a) {
    asm("mul.rn.f32x2 %0, %0, %1;" : "+l"(d) : "l"(a));
}
__device__ __forceinline__ float2 upk(u64 v) {
    int lo, hi;
    asm("mov.b64 {%0, %1}, %2;" : "=r"(lo), "=r"(hi) : "l"(v));
    float2 r; r.x = __int_as_float(lo); r.y = __int_as_float(hi);
    return r;
}
template<int C_> __device__ __forceinline__ float getc(const float4& v) {
    return (C_ == 0) ? v.x : (C_ == 1) ? v.y : (C_ == 2) ? v.z : v.w;
}

// ---------------------------------------------------------------------------
// GEMM, f32x2 inner loop, register-prefetch double buffering.
// out[M,N] = A[M,K] @ W[K,N] + bias.  BM=BN=128, BK=16, 256 thr, 8x8/thread.
// FUSED=1: A = input x, blockIdx.z selects (Wq,bq)->g_q / (Wk,bk)->g_k / (Wv,bv)->g_v
// FUSED=0: A = g_y, (W0,b0) -> out  (final projection)
// ---------------------------------------------------------------------------
template<int FUSED>
__global__ __launch_bounds__(256)
void gemm_f32x2(const float* __restrict__ A_in,
                const float* __restrict__ W0, const float* __restrict__ b0,
                const float* __restrict__ W1, const float* __restrict__ b1,
                const float* __restrict__ W2, const float* __restrict__ b2,
                float* __restrict__ out)
{
    __shared__ __align__(16) float As[2][16][132];  // A tile transposed [k][m]
    __shared__ __align__(16) float Ws[2][16][128];  // W tile [k][n]

    const float* A;
    const float* W;
    const float* bias;
    float* dst;
    if (FUSED) {
        const int z = blockIdx.z;
        A    = A_in;
        W    = (z == 0) ? W0 : (z == 1) ? W1 : W2;
        bias = (z == 0) ? b0 : (z == 1) ? b1 : b2;
        dst  = (z == 0) ? g_q : (z == 1) ? g_k : g_v;
    } else {
        A = g_y; W = W0; bias = b0; dst = out;
    }

    const int bm  = blockIdx.y * 128;
    const int bn  = blockIdx.x * 128;
    const int tid = threadIdx.x;
    const int tx  = tid & 15;
    const int ty  = tid >> 4;

    const int ar  = tid >> 2;   // 0..63
    const int ac4 = tid & 3;    // 0..3
    const int wr  = tid >> 5;   // 0..7
    const int wc  = tid & 31;   // 0..31

    // Packed accumulators: rows ty*4+{0..3}, ty*4+64..67;
    // col pairs: [0]=(tx*4+0,1) [1]=(tx*4+2,3) [2]=(+64+0,1) [3]=(+64+2,3)
    u64 acc[8][4];
    #pragma unroll
    for (int i = 0; i < 8; ++i)
        #pragma unroll
        for (int j = 0; j < 4; ++j) acc[i][j] = 0ull;

    // Preload tile 0 into buffer 0
    {
        #pragma unroll
        for (int i = 0; i < 2; ++i) {
            int row = ar + i*64;
            float4 v = *(const float4*)&A[(size_t)(bm + row)*CC + ac4*4];
            As[0][ac4*4+0][row] = v.x;
            As[0][ac4*4+1][row] = v.y;
            As[0][ac4*4+2][row] = v.z;
            As[0][ac4*4+3][row] = v.w;
        }
        #pragma unroll
        for (int i = 0; i < 2; ++i)
            *(float4*)&Ws[0][wr + i*8][wc*4] =
                *(const float4*)&W[(size_t)(wr + i*8)*CC + bn + wc*4];
    }
    __syncthreads();

    const int NT = CC / 16;   // 64
    float4 pa0, pa1, pw0, pw1;

    for (int kt = 0; kt < NT; ++kt) {
        const int cur = kt & 1;
        // Prefetch next tile into registers (overlaps with compute)
        if (kt + 1 < NT) {
            const int kb = (kt + 1) * 16;
            pa0 = *(const float4*)&A[(size_t)(bm + ar     )*CC + kb + ac4*4];
            pa1 = *(const float4*)&A[(size_t)(bm + ar + 64)*CC + kb + ac4*4];
            pw0 = *(const float4*)&W[(size_t)(kb + wr    )*CC + bn + wc*4];
            pw1 = *(const float4*)&W[(size_t)(kb + wr + 8)*CC + bn + wc*4];
        }

        // Compute on current buffer
        #pragma unroll
        for (int k = 0; k < 16; ++k) {
            float4 a0 = *(const float4*)&As[cur][k][ty*4];
            float4 a1 = *(const float4*)&As[cur][k][ty*4 + 64];
            ulonglong2 w0 = *(const ulonglong2*)&Ws[cur][k][tx*4];       // (n0,n1),(n2,n3)
            ulonglong2 w1 = *(const ulonglong2*)&Ws[cur][k][tx*4 + 64];
            float a[8] = {a0.x,a0.y,a0.z,a0.w, a1.x,a1.y,a1.z,a1.w};
            #pragma unroll
            for (int i = 0; i < 8; ++i) {
                u64 ai = pk2f(a[i], a[i]);
                fma2(acc[i][0], ai, w0.x);
                fma2(acc[i][1], ai, w0.y);
                fma2(acc[i][2], ai, w1.x);
                fma2(acc[i][3], ai, w1.y);
            }
        }

        // Stage prefetched tile into the other buffer
        if (kt + 1 < NT) {
            const int nxt = cur ^ 1;
            As[nxt][ac4*4+0][ar]      = pa0.x;
            As[nxt][ac4*4+1][ar]      = pa0.y;
            As[nxt][ac4*4+2][ar]      = pa0.z;
            As[nxt][ac4*4+3][ar]      = pa0.w;
            As[nxt][ac4*4+0][ar + 64] = pa1.x;
            As[nxt][ac4*4+1][ar + 64] = pa1.y;
            As[nxt][ac4*4+2][ar + 64] = pa1.z;
            As[nxt][ac4*4+3][ar + 64] = pa1.w;
            *(float4*)&Ws[nxt][wr    ][wc*4] = pw0;
            *(float4*)&Ws[nxt][wr + 8][wc*4] = pw1;
        }
        __syncthreads();
    }

    // Epilogue
    #pragma unroll
    for (int i = 0; i < 8; ++i) {
        int m = bm + ty*4 + ((i < 4) ? i : (60 + i));
        int b = m >> 11;
        int t = m & (TT - 1);
        #pragma unroll
        for (int jg = 0; jg < 2; ++jg) {
            int n = bn + tx*4 + jg*64;
            float4 bi = *(const float4*)&bias[n];
            float2 p0 = upk(acc[i][jg*2 + 0]);
            float2 p1 = upk(acc[i][jg*2 + 1]);
            float4 v;
            v.x = p0.x + bi.x;  v.y = p0.y + bi.y;
            v.z = p1.x + bi.z;  v.w = p1.y + bi.w;
            if (!FUSED) {
                *(float4*)&dst[(size_t)m*CC + n] = v;
            } else {
                int h  = n >> 6;
                int dd = n & 63;
                *(float4*)&dst[(((size_t)b*HH + h)*TT + t)*DD + dd] = v;
            }
        }
    }
}

// ---------------------------------------------------------------------------
// Flash attention (fp32, causal). BM=128 query rows, BN=64 keys per tile.
// 256 threads as 16x16; 8x4 micro-tiles; f32x2 packed FMA in S and PV phases;
// register-resident online softmax (width-16 shfl row reductions).
// ---------------------------------------------------------------------------
#define FSTR 68
#define FLASH_SMEM ((128*FSTR + 64*FSTR + 64*FSTR + 128*FSTR) * (int)sizeof(float))

__global__ __launch_bounds__(256)
void flash_attn()
{
    extern __shared__ float sm[];
    float* Qs = sm;                   // [128][68]  (Q, pre-scaled by 1/sqrt(d))
    float* Ks = Qs + 128*FSTR;        // [64][68]
    float* Vs = Ks + 64*FSTR;         // [64][68]
    float* Ss = Vs + 64*FSTR;         // [128][68]  probabilities P

    const int qb  = (gridDim.x - 1) - blockIdx.x;   // heavy blocks first
    const int bh  = blockIdx.y;
    const int b   = bh >> 4;
    const int h   = bh & 15;
    const int tid = threadIdx.x;
    const int tx  = tid & 15;
    const int ty  = tid >> 4;

    const float* qptr = g_q + ((size_t)bh*TT + qb*128)*DD;
    const float* kptr = g_k + (size_t)bh*TT*DD;
    const float* vptr = g_v + (size_t)bh*TT*DD;

    // Load Q tile, scaled by 1/sqrt(64)=0.125
    #pragma unroll
    for (int i = 0; i < 8; ++i) {
        int lin = tid + i*256;
        int r = lin >> 4, d4 = lin & 15;
        float4 v = *(const float4*)&qptr[r*DD + d4*4];
        v.x *= 0.125f; v.y *= 0.125f; v.z *= 0.125f; v.w *= 0.125f;
        *(float4*)&Qs[r*FSTR + d4*4] = v;
    }

    u64 o2[8][2];                    // rows ty+16i; dim pairs (tx*4+0,1),(tx*4+2,3)
    float mrow[8], lrow[8];
    #pragma unroll
    for (int i = 0; i < 8; ++i) {
        o2[i][0] = 0ull; o2[i][1] = 0ull;
        mrow[i] = -1e30f; lrow[i] = 0.f;
    }

    const int ntile = 2*qb + 2;
    for (int kt = 0; kt < ntile; ++kt) {
        __syncthreads();   // prior PV reads of Ss/Vs + S reads of Ks done
        #pragma unroll
        for (int i = 0; i < 4; ++i) {
            int lin = tid + i*256;
            int r = lin >> 4, d4 = lin & 15;
            *(float4*)&Ks[r*FSTR + d4*4] = *(const float4*)&kptr[(kt*64 + r)*DD + d4*4];
            *(float4*)&Vs[r*FSTR + d4*4] = *(const float4*)&vptr[(kt*64 + r)*DD + d4*4];
        }
        __syncthreads();

        // ---- S = Q @ K^T : packed pairs over col-pairs (j0,j1) and (j2,j3)
        u64 s2[8][2];
        #pragma unroll
        for (int i = 0; i < 8; ++i) { s2[i][0] = 0ull; s2[i][1] = 0ull; }

        #pragma unroll 4
        for (int k4 = 0; k4 < 16; ++k4) {
            float4 qv[8], kv[4];
            #pragma unroll
            for (int i = 0; i < 8; ++i)
                qv[i] = *(const float4*)&Qs[(ty + 16*i)*FSTR + k4*4];
            #pragma unroll
            for (int j = 0; j < 4; ++j)
                kv[j] = *(const float4*)&Ks[(tx + 16*j)*FSTR + k4*4];

            #define S_STEP(CMP_) {                                           \
                u64 kp0 = pk2f(getc<CMP_>(kv[0]), getc<CMP_>(kv[1]));        \
                u64 kp1 = pk2f(getc<CMP_>(kv[2]), getc<CMP_>(kv[3]));        \
                _Pragma("unroll")                                            \
                for (int i = 0; i < 8; ++i) {                                \
                    float q = getc<CMP_>(qv[i]);                             \
                    u64 qq = pk2f(q, q);                                     \
                    fma2(s2[i][0], qq, kp0);                                 \
                    fma2(s2[i][1], qq, kp1);                                 \
                }                                                            \
            }
            S_STEP(0) S_STEP(1) S_STEP(2) S_STEP(3)
            #undef S_STEP
        }

        // unpack: s[i][j] is score at (row ty+16i, col tx+16j)
        float s[8][4];
        #pragma unroll
        for (int i = 0; i < 8; ++i) {
            float2 u0 = upk(s2[i][0]);
            float2 u1 = upk(s2[i][1]);
            s[i][0] = u0.x; s[i][1] = u0.y; s[i][2] = u1.x; s[i][3] = u1.y;
        }

        // causal mask (only the last two tiles can touch the diagonal)
        if (kt >= 2*qb) {
            const int rb = qb*128 + ty;
            const int cb = kt*64 + tx;
            #pragma unroll
            for (int i = 0; i < 8; ++i)
                #pragma unroll
                for (int j = 0; j < 4; ++j)
                    if (cb + 16*j > rb + 16*i) s[i][j] = -1e30f;
        }

        // ---- register online softmax (row spans the 16 tx lanes of a half-warp)
        #pragma unroll
        for (int i = 0; i < 8; ++i) {
            float mx = fmaxf(fmaxf(s[i][0], s[i][1]), fmaxf(s[i][2], s[i][3]));
            mx = fmaxf(mx, __shfl_xor_sync(0xffffffffu, mx, 1));
            mx = fmaxf(mx, __shfl_xor_sync(0xffffffffu, mx, 2));
            mx = fmaxf(mx, __shfl_xor_sync(0xffffffffu, mx, 4));
            mx = fmaxf(mx, __shfl_xor_sync(0xffffffffu, mx, 8));
            float mnew = fmaxf(mrow[i], mx);
            float al   = __expf(mrow[i] - mnew);
            float p0 = __expf(s[i][0] - mnew);
            float p1 = __expf(s[i][1] - mnew);
            float p2 = __expf(s[i][2] - mnew);
            float p3 = __expf(s[i][3] - mnew);
            float rs = (p0 + p1) + (p2 + p3);
            rs += __shfl_xor_sync(0xffffffffu, rs, 1);
            rs += __shfl_xor_sync(0xffffffffu, rs, 2);
            rs += __shfl_xor_sync(0xffffffffu, rs, 4);
            rs += __shfl_xor_sync(0xffffffffu, rs, 8);
            lrow[i] = lrow[i]*al + rs;
            mrow[i] = mnew;
            u64 a2 = pk2f(al, al);
            mul2(o2[i][0], a2);
            mul2(o2[i][1], a2);
            const int r = ty + 16*i;
            Ss[r*FSTR + tx     ] = p0;
            Ss[r*FSTR + tx + 16] = p1;
            Ss[r*FSTR + tx + 32] = p2;
            Ss[r*FSTR + tx + 48] = p3;
        }
        __syncthreads();

        // ---- O += P @ V : packed pairs over adjacent dims
        #pragma unroll 4
        for (int c4 = 0; c4 < 16; ++c4) {
            float4 ps[8];
            #pragma unroll
            for (int i = 0; i < 8; ++i)
                ps[i] = *(const float4*)&Ss[(ty + 16*i)*FSTR + c4*4];

            #define PV_STEP(CMP_, CC_) {                                         \
                ulonglong2 vp = *(const ulonglong2*)&Vs[(c4*4 + CC_)*FSTR + tx*4];\
                _Pragma("unroll")                                                 \
                for (int i = 0; i < 8; ++i) {                                     \
                    float p = getc<CMP_>(ps[i]);                                  \
                    u64 pp = pk2f(p, p);                                          \
                    fma2(o2[i][0], pp, vp.x);                                     \
                    fma2(o2[i][1], pp, vp.y);                                     \
                }                                                                 \
            }
            PV_STEP(0, 0) PV_STEP(1, 1) PV_STEP(2, 2) PV_STEP(3, 3)
            #undef PV_STEP
        }
    }

    // normalize + write y as [b,t,c]
    #pragma unroll
    for (int i = 0; i < 8; ++i) {
        float inv = 1.f / lrow[i];
        float2 u0 = upk(o2[i][0]);
        float2 u1 = upk(o2[i][1]);
        int trow = qb*128 + ty + 16*i;
        float4 v;
        v.x = u0.x*inv; v.y = u0.y*inv; v.z = u1.x*inv; v.w = u1.y*inv;
        *(float4*)&g_y[((size_t)b*TT + trow)*CC + h*DD + tx*4] = v;
    }
}

// ---------------------------------------------------------------------------
// Launch
// ---------------------------------------------------------------------------
extern "C" void kernel_launch(void* const* d_in, const int* in_sizes, int n_in,
                              void* d_out, int out_size)
{
    const float* x  = (const float*)d_in[0];
    const float* Wq = (const float*)d_in[1];
    const float* bq = (const float*)d_in[2];
    const float* Wk = (const float*)d_in[3];
    const float* bk = (const float*)d_in[4];
    const float* Wv = (const float*)d_in[5];
    const float* bv = (const float*)d_in[6];
    const float* Wp = (const float*)d_in[7];
    const float* bp = (const float*)d_in[8];
    float* out = (float*)d_out;

    // Fused QKV projections: one launch, z selects weight/dst
    gemm_f32x2<1><<<dim3(CC/128, MM/128, 3), 256>>>(
        x, Wq, bq, Wk, bk, Wv, bv, nullptr);

    cudaFuncSetAttribute(flash_attn,
                         cudaFuncAttributeMaxDynamicSharedMemorySize, FLASH_SMEM);
    flash_attn<<<dim3(TT/128, BB*HH), 256, FLASH_SMEM>>>();

    // Output projection
    gemm_f32x2<0><<<dim3(CC/128, MM/128, 1), 256>>>(
        nullptr, Wp, bp, nullptr, nullptr, nullptr, nullptr, out);
}

// round 14
// speedup vs baseline: 1.0501x; 1.0501x over previous
#include <cuda_runtime.h>

// Problem constants (B,T,C,H = 2,2048,1024,16)
#define BB 2
#define TT 2048
#define CC 1024
#define HH 16
#define DD 64
#define MM (BB*TT)   // 4096

typedef unsigned long long u64;

// ---------------------------------------------------------------------------
// Scratch (static device globals — no allocation APIs anywhere)
// ---------------------------------------------------------------------------
__device__ float g_q[BB*HH*TT*DD];   // [b,h,t,d]
__device__ float g_k[BB*HH*TT*DD];
__device__ float g_v[BB*HH*TT*DD];
__device__ float g_y[BB*TT*CC];      // attention output, [b,t,c]

// ---------------------------------------------------------------------------
// f32x2 packed-math helpers (FFMA2 — ptxas never auto-generates these)
// ---------------------------------------------------------------------------
__device__ __forceinline__ u64 pk2f(float lo, float hi) {
    u64 r;
    asm("mov.b64 %0, {%1, %2};" : "=l"(r)
        : "r"(__float_as_int(lo)), "r"(__float_as_int(hi)));
    return r;
}
__device__ __forceinline__ void fma2(u64& d, u64 a, u64 b) {
    asm("fma.rn.f32x2 %0, %1, %2, %0;" : "+l"(d) : "l"(a), "l"(b));
}
__device__ __forceinline__ void mul2(u64& d, u64 a) {
    asm("mul.rn.f32x2 %0, %0, %1;" : "+l"(d) : "l"(a));
}
__device__ __forceinline__ float2 upk(u64 v) {
    int lo, hi;
    asm("mov.b64 {%0, %1}, %2;" : "=r"(lo), "=r"(hi) : "l"(v));
    float2 r; r.x = __int_as_float(lo); r.y = __int_as_float(hi);
    return r;
}
template<int C_> __device__ __forceinline__ float getc(const float4& v) {
    return (C_ == 0) ? v.x : (C_ == 1) ? v.y : (C_ == 2) ? v.z : v.w;
}

// ---------------------------------------------------------------------------
// GEMM, f32x2 inner loop, register-prefetch double buffering.
// out[M,N] = A[M,K] @ W[K,N] + bias.  BM=BN=128, BK=16, 256 thr, 8x8/thread.
// FUSED=1: A = input x, blockIdx.z selects (Wq,bq)->g_q / (Wk,bk)->g_k / (Wv,bv)->g_v
// FUSED=0: A = g_y, (W0,b0) -> out  (final projection)
// ---------------------------------------------------------------------------
template<int FUSED>
__global__ __launch_bounds__(256)
void gemm_f32x2(const float* __restrict__ A_in,
                const float* __restrict__ W0, const float* __restrict__ b0,
                const float* __restrict__ W1, const float* __restrict__ b1,
                const float* __restrict__ W2, const float* __restrict__ b2,
                float* __restrict__ out)
{
    __shared__ __align__(16) float As[2][16][132];  // A tile transposed [k][m]
    __shared__ __align__(16) float Ws[2][16][128];  // W tile [k][n]

    const float* A;
    const float* W;
    const float* bias;
    float* dst;
    if (FUSED) {
        const int z = blockIdx.z;
        A    = A_in;
        W    = (z == 0) ? W0 : (z == 1) ? W1 : W2;
        bias = (z == 0) ? b0 : (z == 1) ? b1 : b2;
        dst  = (z == 0) ? g_q : (z == 1) ? g_k : g_v;
    } else {
        A = g_y; W = W0; bias = b0; dst = out;
    }

    const int bm  = blockIdx.y * 128;
    const int bn  = blockIdx.x * 128;
    const int tid = threadIdx.x;
    const int tx  = tid & 15;
    const int ty  = tid >> 4;

    const int ar  = tid >> 2;   // 0..63
    const int ac4 = tid & 3;    // 0..3
    const int wr  = tid >> 5;   // 0..7
    const int wc  = tid & 31;   // 0..31

    u64 acc[8][4];
    #pragma unroll
    for (int i = 0; i < 8; ++i)
        #pragma unroll
        for (int j = 0; j < 4; ++j) acc[i][j] = 0ull;

    // Preload tile 0 into buffer 0
    {
        #pragma unroll
        for (int i = 0; i < 2; ++i) {
            int row = ar + i*64;
            float4 v = *(const float4*)&A[(size_t)(bm + row)*CC + ac4*4];
            As[0][ac4*4+0][row] = v.x;
            As[0][ac4*4+1][row] = v.y;
            As[0][ac4*4+2][row] = v.z;
            As[0][ac4*4+3][row] = v.w;
        }
        #pragma unroll
        for (int i = 0; i < 2; ++i)
            *(float4*)&Ws[0][wr + i*8][wc*4] =
                *(const float4*)&W[(size_t)(wr + i*8)*CC + bn + wc*4];
    }
    __syncthreads();

    const int NT = CC / 16;   // 64
    float4 pa0, pa1, pw0, pw1;

    for (int kt = 0; kt < NT; ++kt) {
        const int cur = kt & 1;
        if (kt + 1 < NT) {
            const int kb = (kt + 1) * 16;
            pa0 = *(const float4*)&A[(size_t)(bm + ar     )*CC + kb + ac4*4];
            pa1 = *(const float4*)&A[(size_t)(bm + ar + 64)*CC + kb + ac4*4];
            pw0 = *(const float4*)&W[(size_t)(kb + wr    )*CC + bn + wc*4];
            pw1 = *(const float4*)&W[(size_t)(kb + wr + 8)*CC + bn + wc*4];
        }

        #pragma unroll
        for (int k = 0; k < 16; ++k) {
            float4 a0 = *(const float4*)&As[cur][k][ty*4];
            float4 a1 = *(const float4*)&As[cur][k][ty*4 + 64];
            ulonglong2 w0 = *(const ulonglong2*)&Ws[cur][k][tx*4];
            ulonglong2 w1 = *(const ulonglong2*)&Ws[cur][k][tx*4 + 64];
            float a[8] = {a0.x,a0.y,a0.z,a0.w, a1.x,a1.y,a1.z,a1.w};
            #pragma unroll
            for (int i = 0; i < 8; ++i) {
                u64 ai = pk2f(a[i], a[i]);
                fma2(acc[i][0], ai, w0.x);
                fma2(acc[i][1], ai, w0.y);
                fma2(acc[i][2], ai, w1.x);
                fma2(acc[i][3], ai, w1.y);
            }
        }

        if (kt + 1 < NT) {
            const int nxt = cur ^ 1;
            As[nxt][ac4*4+0][ar]      = pa0.x;
            As[nxt][ac4*4+1][ar]      = pa0.y;
            As[nxt][ac4*4+2][ar]      = pa0.z;
            As[nxt][ac4*4+3][ar]      = pa0.w;
            As[nxt][ac4*4+0][ar + 64] = pa1.x;
            As[nxt][ac4*4+1][ar + 64] = pa1.y;
            As[nxt][ac4*4+2][ar + 64] = pa1.z;
            As[nxt][ac4*4+3][ar + 64] = pa1.w;
            *(float4*)&Ws[nxt][wr    ][wc*4] = pw0;
            *(float4*)&Ws[nxt][wr + 8][wc*4] = pw1;
        }
        __syncthreads();
    }

    #pragma unroll
    for (int i = 0; i < 8; ++i) {
        int m = bm + ty*4 + ((i < 4) ? i : (60 + i));
        int b = m >> 11;
        int t = m & (TT - 1);
        #pragma unroll
        for (int jg = 0; jg < 2; ++jg) {
            int n = bn + tx*4 + jg*64;
            float4 bi = *(const float4*)&bias[n];
            float2 p0 = upk(acc[i][jg*2 + 0]);
            float2 p1 = upk(acc[i][jg*2 + 1]);
            float4 v;
            v.x = p0.x + bi.x;  v.y = p0.y + bi.y;
            v.z = p1.x + bi.z;  v.w = p1.y + bi.w;
            if (!FUSED) {
                *(float4*)&dst[(size_t)m*CC + n] = v;
            } else {
                int h  = n >> 6;
                int dd = n & 63;
                *(float4*)&dst[(((size_t)b*HH + h)*TT + t)*DD + dd] = v;
            }
        }
    }
}

// ---------------------------------------------------------------------------
// Flash attention (fp32, causal). BM=128 query rows x BN=128 keys per tile.
// 256 threads as 16x16; 8x8 micro-tile on S (rows ty+16i, cols tx+16j),
// 8x4 on O (dims tx*4..+3). f32x2 packed FMA everywhere. Q loads are warp
// broadcasts (ty-only address) -> S phase is FMA-bound, not LDS-bound.
// ---------------------------------------------------------------------------
#define FSTR 68
#define PSTR 132
#define FLASH_SMEM ((3*128*FSTR + 128*PSTR) * (int)sizeof(float))   // 172032 B

__global__ __launch_bounds__(256, 1)
void flash_attn()
{
    extern __shared__ float sm[];
    float* Qs = sm;                   // [128][68]  Q, pre-scaled
    float* Ks = Qs + 128*FSTR;        // [128][68]
    float* Vs = Ks + 128*FSTR;        // [128][68]
    float* Ss = Vs + 128*FSTR;        // [128][132] probabilities P

    const int qb  = (gridDim.x - 1) - blockIdx.x;   // heavy blocks first
    const int bh  = blockIdx.y;
    const int b   = bh >> 4;
    const int h   = bh & 15;
    const int tid = threadIdx.x;
    const int tx  = tid & 15;
    const int ty  = tid >> 4;

    const float* qptr = g_q + ((size_t)bh*TT + qb*128)*DD;
    const float* kptr = g_k + (size_t)bh*TT*DD;
    const float* vptr = g_v + (size_t)bh*TT*DD;

    // Load Q tile (128x64), scaled by 1/sqrt(64)
    #pragma unroll
    for (int i = 0; i < 8; ++i) {
        int lin = tid + i*256;
        int r = lin >> 4, d4 = lin & 15;
        float4 v = *(const float4*)&qptr[r*DD + d4*4];
        v.x *= 0.125f; v.y *= 0.125f; v.z *= 0.125f; v.w *= 0.125f;
        *(float4*)&Qs[r*FSTR + d4*4] = v;
    }

    u64 o2[8][2];                    // rows ty+16i; dim pairs (4tx+0,1),(4tx+2,3)
    float mrow[8], lrow[8];
    #pragma unroll
    for (int i = 0; i < 8; ++i) {
        o2[i][0] = 0ull; o2[i][1] = 0ull;
        mrow[i] = -1e30f; lrow[i] = 0.f;
    }

    const int ntile = qb + 1;
    for (int kt = 0; kt < ntile; ++kt) {
        __syncthreads();   // prev iter's reads of Ks/Vs/Ss complete
        // Load K,V tiles (128x64 each)
        #pragma unroll
        for (int i = 0; i < 8; ++i) {
            int lin = tid + i*256;
            int r = lin >> 4, d4 = lin & 15;
            *(float4*)&Ks[r*FSTR + d4*4] = *(const float4*)&kptr[(kt*128 + r)*DD + d4*4];
            *(float4*)&Vs[r*FSTR + d4*4] = *(const float4*)&vptr[(kt*128 + r)*DD + d4*4];
        }
        __syncthreads();

        // ---- S = Q @ K^T : 8 rows x 8 cols per thread, cols packed in pairs
        u64 s2[8][4];
        #pragma unroll
        for (int i = 0; i < 8; ++i)
            #pragma unroll
            for (int p = 0; p < 4; ++p) s2[i][p] = 0ull;

        #pragma unroll 2
        for (int k4 = 0; k4 < 16; ++k4) {
            float4 qv[8], kv[8];
            #pragma unroll
            for (int i = 0; i < 8; ++i)        // broadcast loads (ty-only addr)
                qv[i] = *(const float4*)&Qs[(ty + 16*i)*FSTR + k4*4];
            #pragma unroll
            for (int j = 0; j < 8; ++j)        // conflict-free (tx addr)
                kv[j] = *(const float4*)&Ks[(tx + 16*j)*FSTR + k4*4];

            #define S_STEP(CMP_) {                                           \
                u64 kp0 = pk2f(getc<CMP_>(kv[0]), getc<CMP_>(kv[1]));        \
                u64 kp1 = pk2f(getc<CMP_>(kv[2]), getc<CMP_>(kv[3]));        \
                u64 kp2 = pk2f(getc<CMP_>(kv[4]), getc<CMP_>(kv[5]));        \
                u64 kp3 = pk2f(getc<CMP_>(kv[6]), getc<CMP_>(kv[7]));        \
                _Pragma("unroll")                                            \
                for (int i = 0; i < 8; ++i) {                                \
                    float q = getc<CMP_>(qv[i]);                             \
                    u64 qq = pk2f(q, q);                                     \
                    fma2(s2[i][0], qq, kp0);                                 \
                    fma2(s2[i][1], qq, kp1);                                 \
                    fma2(s2[i][2], qq, kp2);                                 \
                    fma2(s2[i][3], qq, kp3);                                 \
                }                                                            \
            }
            S_STEP(0) S_STEP(1) S_STEP(2) S_STEP(3)
            #undef S_STEP
        }

        // unpack: s[i][jj], col = tx + 16*jj
        float s[8][8];
        #pragma unroll
        for (int i = 0; i < 8; ++i)
            #pragma unroll
            for (int p = 0; p < 4; ++p) {
                float2 u = upk(s2[i][p]);
                s[i][2*p]   = u.x;
                s[i][2*p+1] = u.y;
            }

        // causal mask on the diagonal tile (row/col tile bases are equal)
        if (kt == qb) {
            #pragma unroll
            for (int i = 0; i < 8; ++i)
                #pragma unroll
                for (int jj = 0; jj < 8; ++jj)
                    if (tx + 16*jj > ty + 16*i) s[i][jj] = -1e30f;
        }

        // ---- register online softmax (row spans 16 tx lanes of a half-warp)
        #pragma unroll
        for (int i = 0; i < 8; ++i) {
            float mx = s[i][0];
            #pragma unroll
            for (int jj = 1; jj < 8; ++jj) mx = fmaxf(mx, s[i][jj]);
            mx = fmaxf(mx, __shfl_xor_sync(0xffffffffu, mx, 1));
            mx = fmaxf(mx, __shfl_xor_sync(0xffffffffu, mx, 2));
            mx = fmaxf(mx, __shfl_xor_sync(0xffffffffu, mx, 4));
            mx = fmaxf(mx, __shfl_xor_sync(0xffffffffu, mx, 8));
            float mnew = fmaxf(mrow[i], mx);
            float al   = __expf(mrow[i] - mnew);
            float rs = 0.f;
            const int r = ty + 16*i;
            #pragma unroll
            for (int jj = 0; jj < 8; ++jj) {
                float p = __expf(s[i][jj] - mnew);
                rs += p;
                Ss[r*PSTR + tx + 16*jj] = p;
            }
            rs += __shfl_xor_sync(0xffffffffu, rs, 1);
            rs += __shfl_xor_sync(0xffffffffu, rs, 2);
            rs += __shfl_xor_sync(0xffffffffu, rs, 4);
            rs += __shfl_xor_sync(0xffffffffu, rs, 8);
            lrow[i] = lrow[i]*al + rs;
            mrow[i] = mnew;
            u64 a2 = pk2f(al, al);
            mul2(o2[i][0], a2);
            mul2(o2[i][1], a2);
        }
        // P rows this thread reads in PV are produced within its own warp
        __syncwarp();

        // ---- O += P @ V : 32 c4 steps of 4 key positions each
        #pragma unroll 2
        for (int c4 = 0; c4 < 32; ++c4) {
            float4 ps[8];
            #pragma unroll
            for (int i = 0; i < 8; ++i)        // broadcast loads (ty-only addr)
                ps[i] = *(const float4*)&Ss[(ty + 16*i)*PSTR + c4*4];

            #define PV_STEP(CMP_, CC_) {                                         \
                ulonglong2 vp = *(const ulonglong2*)&Vs[(c4*4 + CC_)*FSTR + tx*4];\
                _Pragma("unroll")                                                 \
                for (int i = 0; i < 8; ++i) {                                     \
                    float p = getc<CMP_>(ps[i]);                                  \
                    u64 pp = pk2f(p, p);                                          \
                    fma2(o2[i][0], pp, vp.x);                                     \
                    fma2(o2[i][1], pp, vp.y);                                     \
                }                                                                 \
            }
            PV_STEP(0, 0) PV_STEP(1, 1) PV_STEP(2, 2) PV_STEP(3, 3)
            #undef PV_STEP
        }
    }

    // normalize + write y as [b,t,c]
    #pragma unroll
    for (int i = 0; i < 8; ++i) {
        float inv = 1.f / lrow[i];
        float2 u0 = upk(o2[i][0]);
        float2 u1 = upk(o2[i][1]);
        int trow = qb*128 + ty + 16*i;
        float4 v;
        v.x = u0.x*inv; v.y = u0.y*inv; v.z = u1.x*inv; v.w = u1.y*inv;
        *(float4*)&g_y[((size_t)b*TT + trow)*CC + h*DD + tx*4] = v;
    }
}

// ---------------------------------------------------------------------------
// Launch
// ---------------------------------------------------------------------------
extern "C" void kernel_launch(void* const* d_in, const int* in_sizes, int n_in,
                              void* d_out, int out_size)
{
    const float* x  = (const float*)d_in[0];
    const float* Wq = (const float*)d_in[1];
    const float* bq = (const float*)d_in[2];
    const float* Wk = (const float*)d_in[3];
    const float* bk = (const float*)d_in[4];
    const float* Wv = (const float*)d_in[5];
    const float* bv = (const float*)d_in[6];
    const float* Wp = (const float*)d_in[7];
    const float* bp = (const float*)d_in[8];
    float* out = (float*)d_out;

    gemm_f32x2<1><<<dim3(CC/128, MM/128, 3), 256>>>(
        x, Wq, bq, Wk, bk, Wv, bv, nullptr);

    cudaFuncSetAttribute(flash_attn,
                         cudaFuncAttributeMaxDynamicSharedMemorySize, FLASH_SMEM);
    flash_attn<<<dim3(TT/128, BB*HH), 256, FLASH_SMEM>>>();

    gemm_f32x2<0><<<dim3(CC/128, MM/128, 1), 256>>>(
        nullptr, Wp, bp, nullptr, nullptr, nullptr, nullptr, out);
}

// round 15
// speedup vs baseline: 1.0508x; 1.0006x over previous
#include <cuda_runtime.h>

// Problem constants (B,T,C,H = 2,2048,1024,16)
#define BB 2
#define TT 2048
#define CC 1024
#define HH 16
#define DD 64
#define MM (BB*TT)   // 4096

typedef unsigned long long u64;

// ---------------------------------------------------------------------------
// Scratch (static device globals — no allocation APIs anywhere)
// ---------------------------------------------------------------------------
__device__ float g_q[BB*HH*TT*DD];   // [b,h,t,d]
__device__ float g_k[BB*HH*TT*DD];
__device__ float g_v[BB*HH*TT*DD];
__device__ float g_y[BB*TT*CC];      // attention output, [b,t,c]

// ---------------------------------------------------------------------------
// f32x2 packed-math helpers (FFMA2 — ptxas never auto-generates these)
// ---------------------------------------------------------------------------
__device__ __forceinline__ u64 pk2f(float lo, float hi) {
    u64 r;
    asm("mov.b64 %0, {%1, %2};" : "=l"(r)
        : "r"(__float_as_int(lo)), "r"(__float_as_int(hi)));
    return r;
}
__device__ __forceinline__ void fma2(u64& d, u64 a, u64 b) {
    asm("fma.rn.f32x2 %0, %1, %2, %0;" : "+l"(d) : "l"(a), "l"(b));
}
__device__ __forceinline__ void mul2(u64& d, u64 a) {
    asm("mul.rn.f32x2 %0, %0, %1;" : "+l"(d) : "l"(a));
}
__device__ __forceinline__ float2 upk(u64 v) {
    int lo, hi;
    asm("mov.b64 {%0, %1}, %2;" : "=r"(lo), "=r"(hi) : "l"(v));
    float2 r; r.x = __int_as_float(lo); r.y = __int_as_float(hi);
    return r;
}
template<int C_> __device__ __forceinline__ float getc(const float4& v) {
    return (C_ == 0) ? v.x : (C_ == 1) ? v.y : (C_ == 2) ? v.z : v.w;
}

// ---------------------------------------------------------------------------
// GEMM, f32x2 inner loop, register-prefetch double buffering.
// out[M,N] = A[M,K] @ W[K,N] + bias.  BM=BN=128, BK=16, 256 thr, 8x8/thread.
// FUSED=1: A = input x, blockIdx.z selects (Wq,bq)->g_q / (Wk,bk)->g_k / (Wv,bv)->g_v
// FUSED=0: A = g_y, (W0,b0) -> out  (final projection)
// ---------------------------------------------------------------------------
template<int FUSED>
__global__ __launch_bounds__(256)
void gemm_f32x2(const float* __restrict__ A_in,
                const float* __restrict__ W0, const float* __restrict__ b0,
                const float* __restrict__ W1, const float* __restrict__ b1,
                const float* __restrict__ W2, const float* __restrict__ b2,
                float* __restrict__ out)
{
    __shared__ __align__(16) float As[2][16][132];  // A tile transposed [k][m]
    __shared__ __align__(16) float Ws[2][16][128];  // W tile [k][n]

    const float* A;
    const float* W;
    const float* bias;
    float* dst;
    if (FUSED) {
        const int z = blockIdx.z;
        A    = A_in;
        W    = (z == 0) ? W0 : (z == 1) ? W1 : W2;
        bias = (z == 0) ? b0 : (z == 1) ? b1 : b2;
        dst  = (z == 0) ? g_q : (z == 1) ? g_k : g_v;
    } else {
        A = g_y; W = W0; bias = b0; dst = out;
    }

    const int bm  = blockIdx.y * 128;
    const int bn  = blockIdx.x * 128;
    const int tid = threadIdx.x;
    const int tx  = tid & 15;
    const int ty  = tid >> 4;

    const int ar  = tid >> 2;   // 0..63
    const int ac4 = tid & 3;    // 0..3
    const int wr  = tid >> 5;   // 0..7
    const int wc  = tid & 31;   // 0..31

    u64 acc[8][4];
    #pragma unroll
    for (int i = 0; i < 8; ++i)
        #pragma unroll
        for (int j = 0; j < 4; ++j) acc[i][j] = 0ull;

    // Preload tile 0 into buffer 0
    {
        #pragma unroll
        for (int i = 0; i < 2; ++i) {
            int row = ar + i*64;
            float4 v = *(const float4*)&A[(size_t)(bm + row)*CC + ac4*4];
            As[0][ac4*4+0][row] = v.x;
            As[0][ac4*4+1][row] = v.y;
            As[0][ac4*4+2][row] = v.z;
            As[0][ac4*4+3][row] = v.w;
        }
        #pragma unroll
        for (int i = 0; i < 2; ++i)
            *(float4*)&Ws[0][wr + i*8][wc*4] =
                *(const float4*)&W[(size_t)(wr + i*8)*CC + bn + wc*4];
    }
    __syncthreads();

    const int NT = CC / 16;   // 64
    float4 pa0, pa1, pw0, pw1;

    for (int kt = 0; kt < NT; ++kt) {
        const int cur = kt & 1;
        if (kt + 1 < NT) {
            const int kb = (kt + 1) * 16;
            pa0 = *(const float4*)&A[(size_t)(bm + ar     )*CC + kb + ac4*4];
            pa1 = *(const float4*)&A[(size_t)(bm + ar + 64)*CC + kb + ac4*4];
            pw0 = *(const float4*)&W[(size_t)(kb + wr    )*CC + bn + wc*4];
            pw1 = *(const float4*)&W[(size_t)(kb + wr + 8)*CC + bn + wc*4];
        }

        #pragma unroll
        for (int k = 0; k < 16; ++k) {
            float4 a0 = *(const float4*)&As[cur][k][ty*4];
            float4 a1 = *(const float4*)&As[cur][k][ty*4 + 64];
            ulonglong2 w0 = *(const ulonglong2*)&Ws[cur][k][tx*4];
            ulonglong2 w1 = *(const ulonglong2*)&Ws[cur][k][tx*4 + 64];
            float a[8] = {a0.x,a0.y,a0.z,a0.w, a1.x,a1.y,a1.z,a1.w};
            #pragma unroll
            for (int i = 0; i < 8; ++i) {
                u64 ai = pk2f(a[i], a[i]);
                fma2(acc[i][0], ai, w0.x);
                fma2(acc[i][1], ai, w0.y);
                fma2(acc[i][2], ai, w1.x);
                fma2(acc[i][3], ai, w1.y);
            }
        }

        if (kt + 1 < NT) {
            const int nxt = cur ^ 1;
            As[nxt][ac4*4+0][ar]      = pa0.x;
            As[nxt][ac4*4+1][ar]      = pa0.y;
            As[nxt][ac4*4+2][ar]      = pa0.z;
            As[nxt][ac4*4+3][ar]      = pa0.w;
            As[nxt][ac4*4+0][ar + 64] = pa1.x;
            As[nxt][ac4*4+1][ar + 64] = pa1.y;
            As[nxt][ac4*4+2][ar + 64] = pa1.z;
            As[nxt][ac4*4+3][ar + 64] = pa1.w;
            *(float4*)&Ws[nxt][wr    ][wc*4] = pw0;
            *(float4*)&Ws[nxt][wr + 8][wc*4] = pw1;
        }
        __syncthreads();
    }

    #pragma unroll
    for (int i = 0; i < 8; ++i) {
        int m = bm + ty*4 + ((i < 4) ? i : (60 + i));
        int b = m >> 11;
        int t = m & (TT - 1);
        #pragma unroll
        for (int jg = 0; jg < 2; ++jg) {
            int n = bn + tx*4 + jg*64;
            float4 bi = *(const float4*)&bias[n];
            float2 p0 = upk(acc[i][jg*2 + 0]);
            float2 p1 = upk(acc[i][jg*2 + 1]);
            float4 v;
            v.x = p0.x + bi.x;  v.y = p0.y + bi.y;
            v.z = p1.x + bi.z;  v.w = p1.y + bi.w;
            if (!FUSED) {
                *(float4*)&dst[(size_t)m*CC + n] = v;
            } else {
                int h  = n >> 6;
                int dd = n & 63;
                *(float4*)&dst[(((size_t)b*HH + h)*TT + t)*DD + dd] = v;
            }
        }
    }
}

// ---------------------------------------------------------------------------
// Flash attention (fp32, causal). BM=128 query rows x BN=128 keys per tile.
// 256 threads as 16x16; 8x8 micro-tile on S (rows ty+16i, cols tx+16j),
// 8x4 on O (dims tx*4..+3). f32x2 packed FMA everywhere. Q loads are warp
// broadcasts (ty-only address) -> S phase is FMA-bound, not LDS-bound.
// ---------------------------------------------------------------------------
#define FSTR 68
#define PSTR 132
#define FLASH_SMEM ((3*128*FSTR + 128*PSTR) * (int)sizeof(float))   // 172032 B

__global__ __launch_bounds__(256, 1)
void flash_attn()
{
    extern __shared__ float sm[];
    float* Qs = sm;                   // [128][68]  Q, pre-scaled
    float* Ks = Qs + 128*FSTR;        // [128][68]
    float* Vs = Ks + 128*FSTR;        // [128][68]
    float* Ss = Vs + 128*FSTR;        // [128][132] probabilities P

    const int qb  = (gridDim.x - 1) - blockIdx.x;   // heavy blocks first
    const int bh  = blockIdx.y;
    const int b   = bh >> 4;
    const int h   = bh & 15;
    const int tid = threadIdx.x;
    const int tx  = tid & 15;
    const int ty  = tid >> 4;

    const float* qptr = g_q + ((size_t)bh*TT + qb*128)*DD;
    const float* kptr = g_k + (size_t)bh*TT*DD;
    const float* vptr = g_v + (size_t)bh*TT*DD;

    // Load Q tile (128x64), scaled by 1/sqrt(64)
    #pragma unroll
    for (int i = 0; i < 8; ++i) {
        int lin = tid + i*256;
        int r = lin >> 4, d4 = lin & 15;
        float4 v = *(const float4*)&qptr[r*DD + d4*4];
        v.x *= 0.125f; v.y *= 0.125f; v.z *= 0.125f; v.w *= 0.125f;
        *(float4*)&Qs[r*FSTR + d4*4] = v;
    }

    u64 o2[8][2];                    // rows ty+16i; dim pairs (4tx+0,1),(4tx+2,3)
    float mrow[8], lrow[8];
    #pragma unroll
    for (int i = 0; i < 8; ++i) {
        o2[i][0] = 0ull; o2[i][1] = 0ull;
        mrow[i] = -1e30f; lrow[i] = 0.f;
    }

    const int ntile = qb + 1;
    for (int kt = 0; kt < ntile; ++kt) {
        __syncthreads();   // prev iter's reads of Ks/Vs/Ss complete
        // Load K,V tiles (128x64 each)
        #pragma unroll
        for (int i = 0; i < 8; ++i) {
            int lin = tid + i*256;
            int r = lin >> 4, d4 = lin & 15;
            *(float4*)&Ks[r*FSTR + d4*4] = *(const float4*)&kptr[(kt*128 + r)*DD + d4*4];
            *(float4*)&Vs[r*FSTR + d4*4] = *(const float4*)&vptr[(kt*128 + r)*DD + d4*4];
        }
        __syncthreads();

        // ---- S = Q @ K^T : 8 rows x 8 cols per thread, cols packed in pairs
        u64 s2[8][4];
        #pragma unroll
        for (int i = 0; i < 8; ++i)
            #pragma unroll
            for (int p = 0; p < 4; ++p) s2[i][p] = 0ull;

        #pragma unroll 2
        for (int k4 = 0; k4 < 16; ++k4) {
            float4 qv[8], kv[8];
            #pragma unroll
            for (int i = 0; i < 8; ++i)        // broadcast loads (ty-only addr)
                qv[i] = *(const float4*)&Qs[(ty + 16*i)*FSTR + k4*4];
            #pragma unroll
            for (int j = 0; j < 8; ++j)        // conflict-free (tx addr)
                kv[j] = *(const float4*)&Ks[(tx + 16*j)*FSTR + k4*4];

            #define S_STEP(CMP_) {                                           \
                u64 kp0 = pk2f(getc<CMP_>(kv[0]), getc<CMP_>(kv[1]));        \
                u64 kp1 = pk2f(getc<CMP_>(kv[2]), getc<CMP_>(kv[3]));        \
                u64 kp2 = pk2f(getc<CMP_>(kv[4]), getc<CMP_>(kv[5]));        \
                u64 kp3 = pk2f(getc<CMP_>(kv[6]), getc<CMP_>(kv[7]));        \
                _Pragma("unroll")                                            \
                for (int i = 0; i < 8; ++i) {                                \
                    float q = getc<CMP_>(qv[i]);                             \
                    u64 qq = pk2f(q, q);                                     \
                    fma2(s2[i][0], qq, kp0);                                 \
                    fma2(s2[i][1], qq, kp1);                                 \
                    fma2(s2[i][2], qq, kp2);                                 \
                    fma2(s2[i][3], qq, kp3);                                 \
                }                                                            \
            }
            S_STEP(0) S_STEP(1) S_STEP(2) S_STEP(3)
            #undef S_STEP
        }

        // unpack: s[i][jj], col = tx + 16*jj
        float s[8][8];
        #pragma unroll
        for (int i = 0; i < 8; ++i)
            #pragma unroll
            for (int p = 0; p < 4; ++p) {
                float2 u = upk(s2[i][p]);
                s[i][2*p]   = u.x;
                s[i][2*p+1] = u.y;
            }

        // causal mask on the diagonal tile (row/col tile bases are equal)
        if (kt == qb) {
            #pragma unroll
            for (int i = 0; i < 8; ++i)
                #pragma unroll
                for (int jj = 0; jj < 8; ++jj)
                    if (tx + 16*jj > ty + 16*i) s[i][jj] = -1e30f;
        }

        // ---- register online softmax (row spans 16 tx lanes of a half-warp)
        #pragma unroll
        for (int i = 0; i < 8; ++i) {
            float mx = s[i][0];
            #pragma unroll
            for (int jj = 1; jj < 8; ++jj) mx = fmaxf(mx, s[i][jj]);
            mx = fmaxf(mx, __shfl_xor_sync(0xffffffffu, mx, 1));
            mx = fmaxf(mx, __shfl_xor_sync(0xffffffffu, mx, 2));
            mx = fmaxf(mx, __shfl_xor_sync(0xffffffffu, mx, 4));
            mx = fmaxf(mx, __shfl_xor_sync(0xffffffffu, mx, 8));
            float mnew = fmaxf(mrow[i], mx);
            float al   = __expf(mrow[i] - mnew);
            float rs = 0.f;
            const int r = ty + 16*i;
            #pragma unroll
            for (int jj = 0; jj < 8; ++jj) {
                float p = __expf(s[i][jj] - mnew);
                rs += p;
                Ss[r*PSTR + tx + 16*jj] = p;
            }
            rs += __shfl_xor_sync(0xffffffffu, rs, 1);
            rs += __shfl_xor_sync(0xffffffffu, rs, 2);
            rs += __shfl_xor_sync(0xffffffffu, rs, 4);
            rs += __shfl_xor_sync(0xffffffffu, rs, 8);
            lrow[i] = lrow[i]*al + rs;
            mrow[i] = mnew;
            u64 a2 = pk2f(al, al);
            mul2(o2[i][0], a2);
            mul2(o2[i][1], a2);
        }
        // P rows this thread reads in PV are produced within its own warp
        __syncwarp();

        // ---- O += P @ V : 32 c4 steps of 4 key positions each
        #pragma unroll 2
        for (int c4 = 0; c4 < 32; ++c4) {
            float4 ps[8];
            #pragma unroll
            for (int i = 0; i < 8; ++i)        // broadcast loads (ty-only addr)
                ps[i] = *(const float4*)&Ss[(ty + 16*i)*PSTR + c4*4];

            #define PV_STEP(CMP_, CC_) {                                         \
                ulonglong2 vp = *(const ulonglong2*)&Vs[(c4*4 + CC_)*FSTR + tx*4];\
                _Pragma("unroll")                                                 \
                for (int i = 0; i < 8; ++i) {                                     \
                    float p = getc<CMP_>(ps[i]);                                  \
                    u64 pp = pk2f(p, p);                                          \
                    fma2(o2[i][0], pp, vp.x);                                     \
                    fma2(o2[i][1], pp, vp.y);                                     \
                }                                                                 \
            }
            PV_STEP(0, 0) PV_STEP(1, 1) PV_STEP(2, 2) PV_STEP(3, 3)
            #undef PV_STEP
        }
    }

    // normalize + write y as [b,t,c]
    #pragma unroll
    for (int i = 0; i < 8; ++i) {
        float inv = 1.f / lrow[i];
        float2 u0 = upk(o2[i][0]);
        float2 u1 = upk(o2[i][1]);
        int trow = qb*128 + ty + 16*i;
        float4 v;
        v.x = u0.x*inv; v.y = u0.y*inv; v.z = u1.x*inv; v.w = u1.y*inv;
        *(float4*)&g_y[((size_t)b*TT + trow)*CC + h*DD + tx*4] = v;
    }
}

// ---------------------------------------------------------------------------
// Launch
// ---------------------------------------------------------------------------
extern "C" void kernel_launch(void* const* d_in, const int* in_sizes, int n_in,
                              void* d_out, int out_size)
{
    const float* x  = (const float*)d_in[0];
    const float* Wq = (const float*)d_in[1];
    const float* bq = (const float*)d_in[2];
    const float* Wk = (const float*)d_in[3];
    const float* bk = (const float*)d_in[4];
    const float* Wv = (const float*)d_in[5];
    const float* bv = (const float*)d_in[6];
    const float* Wp = (const float*)d_in[7];
    const float* bp = (const float*)d_in[8];
    float* out = (float*)d_out;

    gemm_f32x2<1><<<dim3(CC/128, MM/128, 3), 256>>>(
        x, Wq, bq, Wk, bk, Wv, bv, nullptr);

    cudaFuncSetAttribute(flash_attn,
                         cudaFuncAttributeMaxDynamicSharedMemorySize, FLASH_SMEM);
    flash_attn<<<dim3(TT/128, BB*HH), 256, FLASH_SMEM>>>();

    gemm_f32x2<0><<<dim3(CC/128, MM/128, 1), 256>>>(
        nullptr, Wp, bp, nullptr, nullptr, nullptr, nullptr, out);
}